// round 13
// baseline (speedup 1.0000x reference)
#include <cuda_runtime.h>
#include <cstdint>

#define DEV __device__ __forceinline__
typedef unsigned long long u64;

DEV u64 ffma2(u64 a, u64 b, u64 c){ u64 d; asm("fma.rn.f32x2 %0, %1, %2, %3;" : "=l"(d) : "l"(a), "l"(b), "l"(c)); return d; }
DEV u64 fmul2(u64 a, u64 b){ u64 d; asm("mul.rn.f32x2 %0, %1, %2;" : "=l"(d) : "l"(a), "l"(b)); return d; }
DEV u64 fadd2(u64 a, u64 b){ u64 d; asm("add.rn.f32x2 %0, %1, %2;" : "=l"(d) : "l"(a), "l"(b)); return d; }
DEV u64 pack2(float lo, float hi){ u64 r; asm("mov.b64 %0, {%1,%2};" : "=l"(r) : "f"(lo), "f"(hi)); return r; }
DEV float2 unpack2(u64 v){ float2 r; asm("mov.b64 {%0,%1}, %2;" : "=f"(r.x), "=f"(r.y) : "l"(v)); return r; }

DEV float dot32s(const u64* a, const float* __restrict__ w){
  u64 acc0 = 0ULL, acc1 = 0ULL;
  const ulonglong2* wp = (const ulonglong2*)w;
  #pragma unroll
  for (int i = 0; i < 8; i++){
    ulonglong2 wv = wp[i];
    acc0 = ffma2(a[2*i],   wv.x, acc0);
    acc1 = ffma2(a[2*i+1], wv.y, acc1);
  }
  float2 f = unpack2(fadd2(acc0, acc1));
  return f.x + f.y;
}

DEV float leakyf(float z){ return fmaxf(z, 0.3f*z); }
DEV float geluf(float z){ return 0.5f*z*(1.0f + erff(z*0.70710678118654752440f)); }

constexpr float SCALEc = 0.17677669529663688f;
constexpr float EPSc = 1e-3f;

__device__ float g_h [(size_t)2*512*512*128];   // 256 MB
__device__ float g_x2[(size_t)2*512*512*32];    // 64 MB

// ======================= K1 v2: single region per group, 3 blocks/SM =======================
constexpr int RS = 36;
constexpr int K1_SMF = 8816 + 4*2304;   // 18032 floats = 72,128 B

__global__ void __launch_bounds__(256, 3) k1_attn(
    const float* __restrict__ x,  const float* __restrict__ g1, const float* __restrict__ be1,
    const float* __restrict__ Wq, const float* __restrict__ bq,
    const float* __restrict__ Wkv,const float* __restrict__ bkv,
    const float* __restrict__ btab,
    const float* __restrict__ Wp, const float* __restrict__ bp,
    const float* __restrict__ g2, const float* __restrict__ be2,
    const float* __restrict__ W1, const float* __restrict__ b1m)
{
  extern __shared__ float sm[];
  float* sWq  = sm;            // [32 out][32 in] transposed
  float* sWkv = sm + 1024;     // [64][32]
  float* sWp  = sm + 3072;     // [32][32]
  float* sW1  = sm + 4096;     // [128][32]
  float* svec = sm + 8192;
  float* sbt  = sm + 8576;     // 225
  float* rg   = sm + 8816;     // 4 groups x (64 rows x 36)
  float* sbq  = svec;       float* sbkv = svec + 32;  float* sbp  = svec + 96;  float* sb1 = svec + 128;
  float* sg1  = svec + 256; float* sbe1 = svec + 288; float* sg2  = svec + 320; float* sbe2 = svec + 352;

  const int tid = threadIdx.x;
  for (int i = tid; i < 1024; i += 256) sWq [(i&31)*32 + (i>>5)]  = Wq[i];
  for (int i = tid; i < 2048; i += 256) sWkv[(i&63)*32 + (i>>6)]  = Wkv[i];
  for (int i = tid; i < 1024; i += 256) sWp [(i&31)*32 + (i>>5)]  = Wp[i];
  for (int i = tid; i < 4096; i += 256) sW1 [(i&127)*32 + (i>>7)] = W1[i];
  if (tid < 32)  sbq[tid]  = bq[tid];
  if (tid < 64)  sbkv[tid] = bkv[tid];
  if (tid < 32)  sbp[tid]  = bp[tid];
  if (tid < 128) sb1[tid]  = b1m[tid];
  if (tid < 32){ sg1[tid] = g1[tid]; sbe1[tid] = be1[tid]; sg2[tid] = g2[tid]; sbe2[tid] = be2[tid]; }
  if (tid < 225) sbt[tid] = btab[tid];

  // coop load x -> R regions (coalesced)
  #pragma unroll
  for (int i = 0; i < 8; i++){
    int q = tid + i*256; int gg = q>>9; int tt = (q>>3)&63; int j4 = q&7;
    int w = blockIdx.x*4 + gg; int bb = w>>12, rem = w&4095, wy = rem>>6, wx = rem&63;
    size_t tok = (size_t)bb*262144 + (size_t)(wy*8 + (tt>>3))*512 + wx*8 + (tt&7);
    *(float4*)(rg + gg*2304 + tt*RS + j4*4) = *(const float4*)(x + tok*32 + j4*4);
  }
  __syncthreads();

  const int g = tid >> 6, t = tid & 63;
  const int ty = t >> 3, tx = t & 7;
  float* R = rg + g*2304;
  const int bbias = (tx + 7)*15 + (ty + 7);

  // LN1 from own staged row
  float vv[32];
  #pragma unroll
  for (int i = 0; i < 8; i++){
    float4 r = *(const float4*)(R + t*RS + 4*i);
    vv[4*i] = r.x; vv[4*i+1] = r.y; vv[4*i+2] = r.z; vv[4*i+3] = r.w;
  }
  float mu = 0.f;
  #pragma unroll
  for (int c = 0; c < 32; c++) mu += vv[c];
  mu *= (1.f/32.f);
  float var = 0.f;
  #pragma unroll
  for (int c = 0; c < 32; c++){ float d = vv[c]-mu; var += d*d; }
  var *= (1.f/32.f);
  float rs = rsqrtf(var + EPSc);
  u64 xu[16];
  #pragma unroll
  for (int i = 0; i < 16; i++){
    float a0 = (vv[2*i]  -mu)*rs*sg1[2*i]   + sbe1[2*i];
    float a1 = (vv[2*i+1]-mu)*rs*sg1[2*i+1] + sbe1[2*i+1];
    xu[i] = pack2(a0, a1);
  }

  // q (regs)
  u64 qu[16];
  #pragma unroll
  for (int i = 0; i < 16; i++){
    float a0 = leakyf(dot32s(xu, sWq + (2*i  )*32) + sbq[2*i  ]) * SCALEc;
    float a1 = leakyf(dot32s(xu, sWq + (2*i+1)*32) + sbq[2*i+1]) * SCALEc;
    qu[i] = pack2(a0, a1);
  }
  __syncthreads();   // all x rows consumed -> R reusable

  // k -> R[t]
  #pragma unroll 2
  for (int j = 0; j < 32; j += 4){
    float a0 = leakyf(dot32s(xu, sWkv + (j  )*32) + sbkv[j  ]);
    float a1 = leakyf(dot32s(xu, sWkv + (j+1)*32) + sbkv[j+1]);
    float a2 = leakyf(dot32s(xu, sWkv + (j+2)*32) + sbkv[j+2]);
    float a3 = leakyf(dot32s(xu, sWkv + (j+3)*32) + sbkv[j+3]);
    *(float4*)(R + t*RS + j) = make_float4(a0, a1, a2, a3);
  }
  __syncthreads();

  // scores (k broadcast reads)
  float s[64];
  float mx = -3.0e38f;
  #pragma unroll
  for (int m = 0; m < 64; m++){
    float sc = dot32s(qu, R + m*RS) + sbt[bbias - ((m&7)*15 + (m>>3))];
    s[m] = sc; mx = fmaxf(mx, sc);
  }
  __syncthreads();   // all k reads done

  // v from xu -> R[t]  (xu dies here)
  #pragma unroll 2
  for (int j = 0; j < 32; j += 4){
    float a0 = leakyf(dot32s(xu, sWkv + (32+j  )*32) + sbkv[32+j  ]);
    float a1 = leakyf(dot32s(xu, sWkv + (32+j+1)*32) + sbkv[32+j+1]);
    float a2 = leakyf(dot32s(xu, sWkv + (32+j+2)*32) + sbkv[32+j+2]);
    float a3 = leakyf(dot32s(xu, sWkv + (32+j+3)*32) + sbkv[32+j+3]);
    *(float4*)(R + t*RS + j) = make_float4(a0, a1, a2, a3);
  }
  __syncthreads();

  // softmax + PV
  float l = 0.f;
  #pragma unroll
  for (int m = 0; m < 64; m++){ float p = __expf(s[m]-mx); l += p; s[m] = p; }

  u64 Ou[16];
  #pragma unroll
  for (int i = 0; i < 16; i++) Ou[i] = 0ULL;
  #pragma unroll
  for (int m = 0; m < 64; m++){
    u64 pp = pack2(s[m], s[m]);
    const ulonglong2* vp = (const ulonglong2*)(R + m*RS);
    #pragma unroll
    for (int i = 0; i < 8; i++){
      ulonglong2 vq = vp[i];
      Ou[2*i]   = ffma2(pp, vq.x, Ou[2*i]);
      Ou[2*i+1] = ffma2(pp, vq.y, Ou[2*i+1]);
    }
  }
  {
    float linv = 1.f / l;
    u64 li = pack2(linv, linv);
    #pragma unroll
    for (int i = 0; i < 16; i++) Ou[i] = fmul2(Ou[i], li);
  }
  __syncthreads();   // all v reads done

  // coop reload x -> R (residual)
  #pragma unroll
  for (int i = 0; i < 8; i++){
    int q = tid + i*256; int gg = q>>9; int tt = (q>>3)&63; int j4 = q&7;
    int w = blockIdx.x*4 + gg; int bb = w>>12, rem = w&4095, wy = rem>>6, wx = rem&63;
    size_t tok = (size_t)bb*262144 + (size_t)(wy*8 + (tt>>3))*512 + wx*8 + (tt&7);
    *(float4*)(rg + gg*2304 + tt*RS + j4*4) = *(const float4*)(x + tok*32 + j4*4);
  }
  __syncthreads();

  // proj + residual
  float x2r[32];
  #pragma unroll 2
  for (int j = 0; j < 32; j++) x2r[j] = dot32s(Ou, sWp + j*32) + sbp[j];
  #pragma unroll
  for (int i = 0; i < 8; i++){
    float4 r = *(const float4*)(R + t*RS + 4*i);
    x2r[4*i] += r.x; x2r[4*i+1] += r.y; x2r[4*i+2] += r.z; x2r[4*i+3] += r.w;
  }
  // overwrite own row with x2 (no cross-thread hazard: each thread reads only its own row)
  #pragma unroll
  for (int i = 0; i < 8; i++)
    *(float4*)(R + t*RS + 4*i) = make_float4(x2r[4*i], x2r[4*i+1], x2r[4*i+2], x2r[4*i+3]);

  // LN2 in regs
  mu = 0.f;
  #pragma unroll
  for (int c = 0; c < 32; c++) mu += x2r[c];
  mu *= (1.f/32.f);
  var = 0.f;
  #pragma unroll
  for (int c = 0; c < 32; c++){ float d = x2r[c]-mu; var += d*d; }
  var *= (1.f/32.f);
  rs = rsqrtf(var + EPSc);
  u64 yu[16];
  #pragma unroll
  for (int i = 0; i < 16; i++){
    float a0 = (x2r[2*i]  -mu)*rs*sg2[2*i]   + sbe2[2*i];
    float a1 = (x2r[2*i+1]-mu)*rs*sg2[2*i+1] + sbe2[2*i+1];
    yu[i] = pack2(a0, a1);
  }
  __syncthreads();

  // coop write x2 (coalesced)
  #pragma unroll
  for (int i = 0; i < 8; i++){
    int q = tid + i*256; int gg = q>>9; int tt = (q>>3)&63; int j4 = q&7;
    int w = blockIdx.x*4 + gg; int bb = w>>12, rem = w&4095, wy = rem>>6, wx = rem&63;
    size_t tok = (size_t)bb*262144 + (size_t)(wy*8 + (tt>>3))*512 + wx*8 + (tt&7);
    *(float4*)(g_x2 + tok*32 + j4*4) = *(const float4*)(rg + gg*2304 + tt*RS + j4*4);
  }
  __syncthreads();

  // h = gelu(y @ W1 + b1), 4 quarters, staged + coalesced
  #pragma unroll 1
  for (int qt = 0; qt < 4; qt++){
    float hq[32];
    #pragma unroll 2
    for (int jj = 0; jj < 32; jj += 4){
      int j = qt*32 + jj;
      hq[jj  ] = geluf(dot32s(yu, sW1 + (j  )*32) + sb1[j  ]);
      hq[jj+1] = geluf(dot32s(yu, sW1 + (j+1)*32) + sb1[j+1]);
      hq[jj+2] = geluf(dot32s(yu, sW1 + (j+2)*32) + sb1[j+2]);
      hq[jj+3] = geluf(dot32s(yu, sW1 + (j+3)*32) + sb1[j+3]);
    }
    #pragma unroll
    for (int i = 0; i < 8; i++)
      *(float4*)(R + t*RS + 4*i) = make_float4(hq[4*i], hq[4*i+1], hq[4*i+2], hq[4*i+3]);
    __syncthreads();
    #pragma unroll
    for (int i = 0; i < 8; i++){
      int q = tid + i*256; int gg = q>>9; int tt = (q>>3)&63; int j4 = q&7;
      int w = blockIdx.x*4 + gg; int bb = w>>12, rem = w&4095, wy = rem>>6, wx = rem&63;
      size_t tok = (size_t)bb*262144 + (size_t)(wy*8 + (tt>>3))*512 + wx*8 + (tt&7);
      *(float4*)(g_h + tok*128 + qt*32 + j4*4) = *(const float4*)(rg + gg*2304 + tt*RS + j4*4);
    }
    __syncthreads();
  }
}

// ======================= K2 v3: dense stride 132, 3 blocks/SM =======================
constexpr int PST = 132;
constexpr int K2_SMF = 5444 + 100*PST;   // 18644 floats = 74,576 B

__global__ void __launch_bounds__(256, 3) k2_leff(
    const float* __restrict__ dwk, const float* __restrict__ dwb,
    const float* __restrict__ W2,  const float* __restrict__ b2m,
    float* __restrict__ out)
{
  extern __shared__ float sm[];
  float* sW2  = sm;            // [128 k][32 c]
  float* sdw  = sm + 4096;     // [9 tap][128 ch] stride 132
  float* sdwb = sm + 5284;     // 128
  float* sb2  = sm + 5412;     // 32
  float* st   = sm + 5444;     // 100 x 132 halo; aliased as partial[64 x 132]

  const int tid = threadIdx.x;
  for (int i = tid; i < 4096; i += 256) sW2[i] = W2[i];
  for (int i = tid; i < 1152; i += 256){
    int tap = i >> 7, c = i & 127;
    sdw[tap*132 + c] = dwk[i];
  }
  if (tid < 128) sdwb[tid] = dwb[tid];
  if (tid < 32)  sb2[tid]  = b2m[tid];

  const int blk = blockIdx.x, b = blk >> 12, rem = blk & 4095;
  const int y0 = (rem >> 6)*8, x0 = (rem & 63)*8;

  // stage halo: warp per pixel vector, coalesced 512B, dense layout
  const int wid = tid >> 5, lane = tid & 31;
  for (int vid = wid; vid < 100; vid += 8){
    int r = vid/10, c = vid - r*10;
    int hy = y0 + r - 1, hx = x0 + c - 1;
    float4 val = make_float4(0.f, 0.f, 0.f, 0.f);
    if ((unsigned)hy < 512u && (unsigned)hx < 512u)
      val = *(const float4*)(g_h + ((size_t)b*262144 + (size_t)hy*512 + hx)*128 + lane*4);
    *(float4*)(st + vid*PST + lane*4) = val;
  }
  __syncthreads();

  // conv phase: warp = gq, lane = pixel
  const int gq = wid & 3;
  const int p  = (wid >> 2)*32 + lane;
  const int py = p >> 3, px = p & 7;
  const int cv = (py+1)*10 + (px+1);
  const int cw = gq*32;

  u64 acc[16];
  #pragma unroll
  for (int i = 0; i < 16; i++) acc[i] = pack2(sdwb[cw+2*i], sdwb[cw+2*i+1]);
  #pragma unroll
  for (int ky = 0; ky < 3; ky++){
    #pragma unroll
    for (int kx = 0; kx < 3; kx++){
      const ulonglong2* hp = (const ulonglong2*)(st + (cv + (ky-1)*10 + (kx-1))*PST + cw);
      const ulonglong2* wp = (const ulonglong2*)(sdw + (ky*3+kx)*132 + cw);  // warp-uniform
      #pragma unroll
      for (int i = 0; i < 8; i++){
        ulonglong2 hv = hp[i], wv = wp[i];
        acc[2*i]   = ffma2(hv.x, wv.x, acc[2*i]);
        acc[2*i+1] = ffma2(hv.y, wv.y, acc[2*i+1]);
      }
    }
  }

  float hg[32];
  #pragma unroll
  for (int i = 0; i < 16; i++){
    float2 f = unpack2(acc[i]);
    hg[2*i] = geluf(f.x); hg[2*i+1] = geluf(f.y);
  }
  __syncthreads();   // conv reads of st complete before aliasing

  // GEMM partials: 32 outputs for this pixel over this gq's 32 k
  u64 pacc[16];
  #pragma unroll
  for (int i = 0; i < 16; i++) pacc[i] = 0ULL;
  #pragma unroll 8
  for (int j = 0; j < 32; j++){
    u64 hh = pack2(hg[j], hg[j]);
    const ulonglong2* wr = (const ulonglong2*)(sW2 + (cw + j)*32);  // warp-uniform
    #pragma unroll
    for (int i = 0; i < 8; i++){
      ulonglong2 wv = wr[i];
      pacc[2*i]   = ffma2(hh, wv.x, pacc[2*i]);
      pacc[2*i+1] = ffma2(hh, wv.y, pacc[2*i+1]);
    }
  }
  {
    float* prow = st + p*132 + cw;
    #pragma unroll
    for (int i = 0; i < 8; i++){
      float2 f0 = unpack2(pacc[2*i]), f1 = unpack2(pacc[2*i+1]);
      *(float4*)(prow + 4*i) = make_float4(f0.x, f0.y, f1.x, f1.y);
    }
  }
  __syncthreads();

  // reduce 4 partials + bias + residual
  const int p3 = tid >> 2, g3 = tid & 3, c0 = g3*8;
  float o[8];
  #pragma unroll
  for (int i = 0; i < 8; i++) o[i] = sb2[c0+i];
  #pragma unroll
  for (int gp = 0; gp < 4; gp++){
    const float* pr = st + p3*132 + gp*32 + c0;
    float4 a = *(const float4*)(pr);
    float4 bq4 = *(const float4*)(pr + 4);
    o[0]+=a.x; o[1]+=a.y; o[2]+=a.z; o[3]+=a.w;
    o[4]+=bq4.x; o[5]+=bq4.y; o[6]+=bq4.z; o[7]+=bq4.w;
  }
  const int yy = y0 + (p3>>3), xx = x0 + (p3&7);
  const size_t pbase = ((size_t)b*262144 + (size_t)yy*512 + xx)*32 + c0;
  float4 xa = *(const float4*)(g_x2 + pbase);
  float4 xb = *(const float4*)(g_x2 + pbase + 4);
  *(float4*)(out + pbase)     = make_float4(o[0]+xa.x, o[1]+xa.y, o[2]+xa.z, o[3]+xa.w);
  *(float4*)(out + pbase + 4) = make_float4(o[4]+xb.x, o[5]+xb.y, o[6]+xb.z, o[7]+xb.w);
}

// ======================= launch =======================
extern "C" void kernel_launch(void* const* d_in, const int* in_sizes, int n_in,
                              void* d_out, int out_size)
{
  (void)in_sizes; (void)n_in; (void)out_size;
  const float* x    = (const float*)d_in[0];
  const float* g1   = (const float*)d_in[1];
  const float* be1  = (const float*)d_in[2];
  const float* Wq   = (const float*)d_in[3];
  const float* bq   = (const float*)d_in[4];
  const float* Wkv  = (const float*)d_in[5];
  const float* bkv  = (const float*)d_in[6];
  const float* btab = (const float*)d_in[7];
  const float* Wp   = (const float*)d_in[8];
  const float* bp   = (const float*)d_in[9];
  const float* g2   = (const float*)d_in[10];
  const float* be2  = (const float*)d_in[11];
  const float* W1   = (const float*)d_in[12];
  const float* b1m  = (const float*)d_in[13];
  const float* dwk  = (const float*)d_in[14];
  const float* dwb  = (const float*)d_in[15];
  const float* W2   = (const float*)d_in[16];
  const float* b2m  = (const float*)d_in[17];
  float* out = (float*)d_out;

  cudaFuncSetAttribute(k1_attn, cudaFuncAttributeMaxDynamicSharedMemorySize, K1_SMF*4);
  cudaFuncSetAttribute(k2_leff, cudaFuncAttributeMaxDynamicSharedMemorySize, K2_SMF*4);

  k1_attn<<<2048, 256, K1_SMF*4>>>(x, g1, be1, Wq, bq, Wkv, bkv, btab, Wp, bp, g2, be2, W1, b1m);
  k2_leff<<<8192, 256, K2_SMF*4>>>(dwk, dwb, W2, b2m, out);
}

// round 15
// speedup vs baseline: 1.2310x; 1.2310x over previous
#include <cuda_runtime.h>
#include <cstdint>

#define DEV __device__ __forceinline__
typedef unsigned long long u64;

DEV u64 ffma2(u64 a, u64 b, u64 c){ u64 d; asm("fma.rn.f32x2 %0, %1, %2, %3;" : "=l"(d) : "l"(a), "l"(b), "l"(c)); return d; }
DEV u64 fmul2(u64 a, u64 b){ u64 d; asm("mul.rn.f32x2 %0, %1, %2;" : "=l"(d) : "l"(a), "l"(b)); return d; }
DEV u64 fadd2(u64 a, u64 b){ u64 d; asm("add.rn.f32x2 %0, %1, %2;" : "=l"(d) : "l"(a), "l"(b)); return d; }
DEV u64 pack2(float lo, float hi){ u64 r; asm("mov.b64 %0, {%1,%2};" : "=l"(r) : "f"(lo), "f"(hi)); return r; }
DEV float2 unpack2(u64 v){ float2 r; asm("mov.b64 {%0,%1}, %2;" : "=f"(r.x), "=f"(r.y) : "l"(v)); return r; }

DEV float dot32s(const u64* a, const float* __restrict__ w){
  u64 acc0 = 0ULL, acc1 = 0ULL;
  const ulonglong2* wp = (const ulonglong2*)w;
  #pragma unroll
  for (int i = 0; i < 8; i++){
    ulonglong2 wv = wp[i];
    acc0 = ffma2(a[2*i],   wv.x, acc0);
    acc1 = ffma2(a[2*i+1], wv.y, acc1);
  }
  float2 f = unpack2(fadd2(acc0, acc1));
  return f.x + f.y;
}

DEV float leakyf(float z){ return fmaxf(z, 0.3f*z); }
DEV float geluf(float z){ return 0.5f*z*(1.0f + erff(z*0.70710678118654752440f)); }

constexpr float SCALEc = 0.17677669529663688f;
constexpr float EPSc = 1e-3f;

__device__ float g_h [(size_t)2*512*512*128];   // 256 MB
__device__ float g_x2[(size_t)2*512*512*32];    // 64 MB

// ======================= K1 (R5 known-good: A/B regions, 2 blocks/SM, 128 regs) =======================
constexpr int RS = 36;
constexpr int K1_SMF = 8816 + 4*4608;   // 27248 floats = 108,992 B

__global__ void __launch_bounds__(256, 2) k1_attn(
    const float* __restrict__ x,  const float* __restrict__ g1, const float* __restrict__ be1,
    const float* __restrict__ Wq, const float* __restrict__ bq,
    const float* __restrict__ Wkv,const float* __restrict__ bkv,
    const float* __restrict__ btab,
    const float* __restrict__ Wp, const float* __restrict__ bp,
    const float* __restrict__ g2, const float* __restrict__ be2,
    const float* __restrict__ W1, const float* __restrict__ b1m)
{
  extern __shared__ float sm[];
  float* sWq  = sm;
  float* sWkv = sm + 1024;
  float* sWp  = sm + 3072;
  float* sW1  = sm + 4096;
  float* svec = sm + 8192;
  float* sbt  = sm + 8576;
  float* rg   = sm + 8816;
  float* sbq  = svec;       float* sbkv = svec + 32;  float* sbp  = svec + 96;  float* sb1 = svec + 128;
  float* sg1  = svec + 256; float* sbe1 = svec + 288; float* sg2  = svec + 320; float* sbe2 = svec + 352;

  const int tid = threadIdx.x;
  for (int i = tid; i < 1024; i += 256) sWq [(i&31)*32 + (i>>5)]  = Wq[i];
  for (int i = tid; i < 2048; i += 256) sWkv[(i&63)*32 + (i>>6)]  = Wkv[i];
  for (int i = tid; i < 1024; i += 256) sWp [(i&31)*32 + (i>>5)]  = Wp[i];
  for (int i = tid; i < 4096; i += 256) sW1 [(i&127)*32 + (i>>7)] = W1[i];
  if (tid < 32)  sbq[tid]  = bq[tid];
  if (tid < 64)  sbkv[tid] = bkv[tid];
  if (tid < 32)  sbp[tid]  = bp[tid];
  if (tid < 128) sb1[tid]  = b1m[tid];
  if (tid < 32){ sg1[tid] = g1[tid]; sbe1[tid] = be1[tid]; sg2[tid] = g2[tid]; sbe2[tid] = be2[tid]; }
  if (tid < 225) sbt[tid] = btab[tid];

  #pragma unroll
  for (int i = 0; i < 8; i++){
    int q = tid + i*256; int gg = q>>9; int tt = (q>>3)&63; int j4 = q&7;
    int w = blockIdx.x*4 + gg; int bb = w>>12, rem = w&4095, wy = rem>>6, wx = rem&63;
    size_t tok = (size_t)bb*262144 + (size_t)(wy*8 + (tt>>3))*512 + wx*8 + (tt&7);
    *(float4*)(rg + gg*4608 + tt*RS + j4*4) = *(const float4*)(x + tok*32 + j4*4);
  }
  __syncthreads();

  const int g = tid >> 6, t = tid & 63;
  const int ty = t >> 3, tx = t & 7;
  float* A  = rg + g*4608;
  float* Bb = A + 2304;
  const int bbias = (tx + 7)*15 + (ty + 7);

  float vv[32];
  #pragma unroll
  for (int i = 0; i < 8; i++){
    float4 r = *(const float4*)(A + t*RS + 4*i);
    vv[4*i] = r.x; vv[4*i+1] = r.y; vv[4*i+2] = r.z; vv[4*i+3] = r.w;
  }
  float mu = 0.f;
  #pragma unroll
  for (int c = 0; c < 32; c++) mu += vv[c];
  mu *= (1.f/32.f);
  float var = 0.f;
  #pragma unroll
  for (int c = 0; c < 32; c++){ float d = vv[c]-mu; var += d*d; }
  var *= (1.f/32.f);
  float rs = rsqrtf(var + EPSc);
  u64 xu[16];
  #pragma unroll
  for (int i = 0; i < 16; i++){
    float a0 = (vv[2*i]  -mu)*rs*sg1[2*i]   + sbe1[2*i];
    float a1 = (vv[2*i+1]-mu)*rs*sg1[2*i+1] + sbe1[2*i+1];
    xu[i] = pack2(a0, a1);
  }

  u64 qu[16];
  #pragma unroll
  for (int i = 0; i < 16; i++){
    float a0 = leakyf(dot32s(xu, sWq + (2*i  )*32) + sbq[2*i  ]) * SCALEc;
    float a1 = leakyf(dot32s(xu, sWq + (2*i+1)*32) + sbq[2*i+1]) * SCALEc;
    qu[i] = pack2(a0, a1);
  }
  #pragma unroll 2
  for (int j = 0; j < 32; j += 4){
    float a0 = leakyf(dot32s(xu, sWkv + (j  )*32) + sbkv[j  ]);
    float a1 = leakyf(dot32s(xu, sWkv + (j+1)*32) + sbkv[j+1]);
    float a2 = leakyf(dot32s(xu, sWkv + (j+2)*32) + sbkv[j+2]);
    float a3 = leakyf(dot32s(xu, sWkv + (j+3)*32) + sbkv[j+3]);
    *(float4*)(Bb + t*RS + j) = make_float4(a0, a1, a2, a3);
  }
  #pragma unroll 2
  for (int j = 0; j < 32; j += 4){
    float a0 = leakyf(dot32s(xu, sWkv + (32+j  )*32) + sbkv[32+j  ]);
    float a1 = leakyf(dot32s(xu, sWkv + (32+j+1)*32) + sbkv[32+j+1]);
    float a2 = leakyf(dot32s(xu, sWkv + (32+j+2)*32) + sbkv[32+j+2]);
    float a3 = leakyf(dot32s(xu, sWkv + (32+j+3)*32) + sbkv[32+j+3]);
    *(float4*)(A + t*RS + j) = make_float4(a0, a1, a2, a3);
  }
  __syncthreads();

  float s[64];
  float mx = -3.0e38f;
  #pragma unroll
  for (int m = 0; m < 64; m++){
    float sc = dot32s(qu, Bb + m*RS) + sbt[bbias - ((m&7)*15 + (m>>3))];
    s[m] = sc; mx = fmaxf(mx, sc);
  }
  __syncthreads();

  #pragma unroll
  for (int i = 0; i < 8; i++){
    int q = tid + i*256; int gg = q>>9; int tt = (q>>3)&63; int j4 = q&7;
    int w = blockIdx.x*4 + gg; int bb = w>>12, rem = w&4095, wy = rem>>6, wx = rem&63;
    size_t tok = (size_t)bb*262144 + (size_t)(wy*8 + (tt>>3))*512 + wx*8 + (tt&7);
    *(float4*)(rg + gg*4608 + 2304 + tt*RS + j4*4) = *(const float4*)(x + tok*32 + j4*4);
  }

  float l = 0.f;
  #pragma unroll
  for (int m = 0; m < 64; m++){ float p = __expf(s[m]-mx); l += p; s[m] = p; }

  u64 Ou[16];
  #pragma unroll
  for (int i = 0; i < 16; i++) Ou[i] = 0ULL;
  #pragma unroll
  for (int m = 0; m < 64; m++){
    u64 pp = pack2(s[m], s[m]);
    const ulonglong2* vp = (const ulonglong2*)(A + m*RS);
    #pragma unroll
    for (int i = 0; i < 8; i++){
      ulonglong2 vq = vp[i];
      Ou[2*i]   = ffma2(pp, vq.x, Ou[2*i]);
      Ou[2*i+1] = ffma2(pp, vq.y, Ou[2*i+1]);
    }
  }
  {
    float linv = 1.f / l;
    u64 li = pack2(linv, linv);
    #pragma unroll
    for (int i = 0; i < 16; i++) Ou[i] = fmul2(Ou[i], li);
  }
  __syncthreads();

  float x2r[32];
  #pragma unroll 2
  for (int j = 0; j < 32; j++) x2r[j] = dot32s(Ou, sWp + j*32) + sbp[j];
  #pragma unroll
  for (int i = 0; i < 8; i++){
    float4 r = *(const float4*)(Bb + t*RS + 4*i);
    x2r[4*i] += r.x; x2r[4*i+1] += r.y; x2r[4*i+2] += r.z; x2r[4*i+3] += r.w;
  }
  #pragma unroll
  for (int i = 0; i < 8; i++)
    *(float4*)(A + t*RS + 4*i) = make_float4(x2r[4*i], x2r[4*i+1], x2r[4*i+2], x2r[4*i+3]);

  mu = 0.f;
  #pragma unroll
  for (int c = 0; c < 32; c++) mu += x2r[c];
  mu *= (1.f/32.f);
  var = 0.f;
  #pragma unroll
  for (int c = 0; c < 32; c++){ float d = x2r[c]-mu; var += d*d; }
  var *= (1.f/32.f);
  rs = rsqrtf(var + EPSc);
  u64 yu[16];
  #pragma unroll
  for (int i = 0; i < 16; i++){
    float a0 = (x2r[2*i]  -mu)*rs*sg2[2*i]   + sbe2[2*i];
    float a1 = (x2r[2*i+1]-mu)*rs*sg2[2*i+1] + sbe2[2*i+1];
    yu[i] = pack2(a0, a1);
  }
  __syncthreads();

  #pragma unroll
  for (int i = 0; i < 8; i++){
    int q = tid + i*256; int gg = q>>9; int tt = (q>>3)&63; int j4 = q&7;
    int w = blockIdx.x*4 + gg; int bb = w>>12, rem = w&4095, wy = rem>>6, wx = rem&63;
    size_t tok = (size_t)bb*262144 + (size_t)(wy*8 + (tt>>3))*512 + wx*8 + (tt&7);
    *(float4*)(g_x2 + tok*32 + j4*4) = *(const float4*)(rg + gg*4608 + tt*RS + j4*4);
  }
  __syncthreads();

  #pragma unroll 1
  for (int qt = 0; qt < 4; qt++){
    float hq[32];
    #pragma unroll 2
    for (int jj = 0; jj < 32; jj += 4){
      int j = qt*32 + jj;
      hq[jj  ] = geluf(dot32s(yu, sW1 + (j  )*32) + sb1[j  ]);
      hq[jj+1] = geluf(dot32s(yu, sW1 + (j+1)*32) + sb1[j+1]);
      hq[jj+2] = geluf(dot32s(yu, sW1 + (j+2)*32) + sb1[j+2]);
      hq[jj+3] = geluf(dot32s(yu, sW1 + (j+3)*32) + sb1[j+3]);
    }
    #pragma unroll
    for (int i = 0; i < 8; i++)
      *(float4*)(A + t*RS + 4*i) = make_float4(hq[4*i], hq[4*i+1], hq[4*i+2], hq[4*i+3]);
    __syncthreads();
    #pragma unroll
    for (int i = 0; i < 8; i++){
      int q = tid + i*256; int gg = q>>9; int tt = (q>>3)&63; int j4 = q&7;
      int w = blockIdx.x*4 + gg; int bb = w>>12, rem = w&4095, wy = rem>>6, wx = rem&63;
      size_t tok = (size_t)bb*262144 + (size_t)(wy*8 + (tt>>3))*512 + wx*8 + (tt&7);
      *(float4*)(g_h + tok*128 + qt*32 + j4*4) = *(const float4*)(rg + gg*4608 + tt*RS + j4*4);
    }
    __syncthreads();
  }
}

// ======================= K2 v3 (R13 measured-good: dense stride 132, 3 blocks/SM) =======================
constexpr int PST = 132;
constexpr int K2_SMF = 5444 + 100*PST;   // 18644 floats = 74,576 B

__global__ void __launch_bounds__(256, 3) k2_leff(
    const float* __restrict__ dwk, const float* __restrict__ dwb,
    const float* __restrict__ W2,  const float* __restrict__ b2m,
    float* __restrict__ out)
{
  extern __shared__ float sm[];
  float* sW2  = sm;            // [128 k][32 c]
  float* sdw  = sm + 4096;     // [9 tap][128 ch] stride 132
  float* sdwb = sm + 5284;     // 128
  float* sb2  = sm + 5412;     // 32
  float* st   = sm + 5444;     // 100 x 132 halo; aliased as partial[64 x 132]

  const int tid = threadIdx.x;
  for (int i = tid; i < 4096; i += 256) sW2[i] = W2[i];
  for (int i = tid; i < 1152; i += 256){
    int tap = i >> 7, c = i & 127;
    sdw[tap*132 + c] = dwk[i];
  }
  if (tid < 128) sdwb[tid] = dwb[tid];
  if (tid < 32)  sb2[tid]  = b2m[tid];

  const int blk = blockIdx.x, b = blk >> 12, rem = blk & 4095;
  const int y0 = (rem >> 6)*8, x0 = (rem & 63)*8;

  const int wid = tid >> 5, lane = tid & 31;
  for (int vid = wid; vid < 100; vid += 8){
    int r = vid/10, c = vid - r*10;
    int hy = y0 + r - 1, hx = x0 + c - 1;
    float4 val = make_float4(0.f, 0.f, 0.f, 0.f);
    if ((unsigned)hy < 512u && (unsigned)hx < 512u)
      val = *(const float4*)(g_h + ((size_t)b*262144 + (size_t)hy*512 + hx)*128 + lane*4);
    *(float4*)(st + vid*PST + lane*4) = val;
  }
  __syncthreads();

  const int gq = wid & 3;
  const int p  = (wid >> 2)*32 + lane;
  const int py = p >> 3, px = p & 7;
  const int cv = (py+1)*10 + (px+1);
  const int cw = gq*32;

  u64 acc[16];
  #pragma unroll
  for (int i = 0; i < 16; i++) acc[i] = pack2(sdwb[cw+2*i], sdwb[cw+2*i+1]);
  #pragma unroll
  for (int ky = 0; ky < 3; ky++){
    #pragma unroll
    for (int kx = 0; kx < 3; kx++){
      const ulonglong2* hp = (const ulonglong2*)(st + (cv + (ky-1)*10 + (kx-1))*PST + cw);
      const ulonglong2* wp = (const ulonglong2*)(sdw + (ky*3+kx)*132 + cw);
      #pragma unroll
      for (int i = 0; i < 8; i++){
        ulonglong2 hv = hp[i], wv = wp[i];
        acc[2*i]   = ffma2(hv.x, wv.x, acc[2*i]);
        acc[2*i+1] = ffma2(hv.y, wv.y, acc[2*i+1]);
      }
    }
  }

  float hg[32];
  #pragma unroll
  for (int i = 0; i < 16; i++){
    float2 f = unpack2(acc[i]);
    hg[2*i] = geluf(f.x); hg[2*i+1] = geluf(f.y);
  }
  __syncthreads();

  u64 pacc[16];
  #pragma unroll
  for (int i = 0; i < 16; i++) pacc[i] = 0ULL;
  #pragma unroll 8
  for (int j = 0; j < 32; j++){
    u64 hh = pack2(hg[j], hg[j]);
    const ulonglong2* wr = (const ulonglong2*)(sW2 + (cw + j)*32);
    #pragma unroll
    for (int i = 0; i < 8; i++){
      ulonglong2 wv = wr[i];
      pacc[2*i]   = ffma2(hh, wv.x, pacc[2*i]);
      pacc[2*i+1] = ffma2(hh, wv.y, pacc[2*i+1]);
    }
  }
  {
    float* prow = st + p*132 + cw;
    #pragma unroll
    for (int i = 0; i < 8; i++){
      float2 f0 = unpack2(pacc[2*i]), f1 = unpack2(pacc[2*i+1]);
      *(float4*)(prow + 4*i) = make_float4(f0.x, f0.y, f1.x, f1.y);
    }
  }
  __syncthreads();

  const int p3 = tid >> 2, g3 = tid & 3, c0 = g3*8;
  float o[8];
  #pragma unroll
  for (int i = 0; i < 8; i++) o[i] = sb2[c0+i];
  #pragma unroll
  for (int gp = 0; gp < 4; gp++){
    const float* pr = st + p3*132 + gp*32 + c0;
    float4 a = *(const float4*)(pr);
    float4 bq4 = *(const float4*)(pr + 4);
    o[0]+=a.x; o[1]+=a.y; o[2]+=a.z; o[3]+=a.w;
    o[4]+=bq4.x; o[5]+=bq4.y; o[6]+=bq4.z; o[7]+=bq4.w;
  }
  const int yy = y0 + (p3>>3), xx = x0 + (p3&7);
  const size_t pbase = ((size_t)b*262144 + (size_t)yy*512 + xx)*32 + c0;
  float4 xa = *(const float4*)(g_x2 + pbase);
  float4 xb = *(const float4*)(g_x2 + pbase + 4);
  *(float4*)(out + pbase)     = make_float4(o[0]+xa.x, o[1]+xa.y, o[2]+xa.z, o[3]+xa.w);
  *(float4*)(out + pbase + 4) = make_float4(o[4]+xb.x, o[5]+xb.y, o[6]+xb.z, o[7]+xb.w);
}

// ======================= launch =======================
extern "C" void kernel_launch(void* const* d_in, const int* in_sizes, int n_in,
                              void* d_out, int out_size)
{
  (void)in_sizes; (void)n_in; (void)out_size;
  const float* x    = (const float*)d_in[0];
  const float* g1   = (const float*)d_in[1];
  const float* be1  = (const float*)d_in[2];
  const float* Wq   = (const float*)d_in[3];
  const float* bq   = (const float*)d_in[4];
  const float* Wkv  = (const float*)d_in[5];
  const float* bkv  = (const float*)d_in[6];
  const float* btab = (const float*)d_in[7];
  const float* Wp   = (const float*)d_in[8];
  const float* bp   = (const float*)d_in[9];
  const float* g2   = (const float*)d_in[10];
  const float* be2  = (const float*)d_in[11];
  const float* W1   = (const float*)d_in[12];
  const float* b1m  = (const float*)d_in[13];
  const float* dwk  = (const float*)d_in[14];
  const float* dwb  = (const float*)d_in[15];
  const float* W2   = (const float*)d_in[16];
  const float* b2m  = (const float*)d_in[17];
  float* out = (float*)d_out;

  cudaFuncSetAttribute(k1_attn, cudaFuncAttributeMaxDynamicSharedMemorySize, K1_SMF*4);
  cudaFuncSetAttribute(k2_leff, cudaFuncAttributeMaxDynamicSharedMemorySize, K2_SMF*4);

  k1_attn<<<2048, 256, K1_SMF*4>>>(x, g1, be1, Wq, bq, Wkv, bkv, btab, Wp, bp, g2, be2, W1, b1m);
  k2_leff<<<8192, 256, K2_SMF*4>>>(dwk, dwb, W2, b2m, out);
}

// round 16
// speedup vs baseline: 1.2730x; 1.0341x over previous
#include <cuda_runtime.h>
#include <cstdint>

#define DEV __device__ __forceinline__
typedef unsigned long long u64;

DEV u64 ffma2(u64 a, u64 b, u64 c){ u64 d; asm("fma.rn.f32x2 %0, %1, %2, %3;" : "=l"(d) : "l"(a), "l"(b), "l"(c)); return d; }
DEV u64 fmul2(u64 a, u64 b){ u64 d; asm("mul.rn.f32x2 %0, %1, %2;" : "=l"(d) : "l"(a), "l"(b)); return d; }
DEV u64 fadd2(u64 a, u64 b){ u64 d; asm("add.rn.f32x2 %0, %1, %2;" : "=l"(d) : "l"(a), "l"(b)); return d; }
DEV u64 pack2(float lo, float hi){ u64 r; asm("mov.b64 %0, {%1,%2};" : "=l"(r) : "f"(lo), "f"(hi)); return r; }
DEV float2 unpack2(u64 v){ float2 r; asm("mov.b64 {%0,%1}, %2;" : "=f"(r.x), "=f"(r.y) : "l"(v)); return r; }

DEV float dot32s(const u64* a, const float* __restrict__ w){
  u64 acc0 = 0ULL, acc1 = 0ULL;
  const ulonglong2* wp = (const ulonglong2*)w;
  #pragma unroll
  for (int i = 0; i < 8; i++){
    ulonglong2 wv = wp[i];
    acc0 = ffma2(a[2*i],   wv.x, acc0);
    acc1 = ffma2(a[2*i+1], wv.y, acc1);
  }
  float2 f = unpack2(fadd2(acc0, acc1));
  return f.x + f.y;
}

DEV float leakyf(float z){ return fmaxf(z, 0.3f*z); }
DEV float geluf(float z){ return 0.5f*z*(1.0f + erff(z*0.70710678118654752440f)); }

constexpr float SCALEc = 0.17677669529663688f;
constexpr float EPSc = 1e-3f;

__device__ float g_h [(size_t)2*512*512*128];   // 256 MB
__device__ float g_x2[(size_t)2*512*512*32];    // 64 MB

// ======================= K1 (known-good: A/B regions, 2 blocks/SM) =======================
constexpr int RS = 36;
constexpr int K1_SMF = 8816 + 4*4608;   // 27248 floats = 108,992 B

__global__ void __launch_bounds__(256, 2) k1_attn(
    const float* __restrict__ x,  const float* __restrict__ g1, const float* __restrict__ be1,
    const float* __restrict__ Wq, const float* __restrict__ bq,
    const float* __restrict__ Wkv,const float* __restrict__ bkv,
    const float* __restrict__ btab,
    const float* __restrict__ Wp, const float* __restrict__ bp,
    const float* __restrict__ g2, const float* __restrict__ be2,
    const float* __restrict__ W1, const float* __restrict__ b1m)
{
  extern __shared__ float sm[];
  float* sWq  = sm;
  float* sWkv = sm + 1024;
  float* sWp  = sm + 3072;
  float* sW1  = sm + 4096;
  float* svec = sm + 8192;
  float* sbt  = sm + 8576;
  float* rg   = sm + 8816;
  float* sbq  = svec;       float* sbkv = svec + 32;  float* sbp  = svec + 96;  float* sb1 = svec + 128;
  float* sg1  = svec + 256; float* sbe1 = svec + 288; float* sg2  = svec + 320; float* sbe2 = svec + 352;

  const int tid = threadIdx.x;
  for (int i = tid; i < 1024; i += 256) sWq [(i&31)*32 + (i>>5)]  = Wq[i];
  for (int i = tid; i < 2048; i += 256) sWkv[(i&63)*32 + (i>>6)]  = Wkv[i];
  for (int i = tid; i < 1024; i += 256) sWp [(i&31)*32 + (i>>5)]  = Wp[i];
  for (int i = tid; i < 4096; i += 256) sW1 [(i&127)*32 + (i>>7)] = W1[i];
  if (tid < 32)  sbq[tid]  = bq[tid];
  if (tid < 64)  sbkv[tid] = bkv[tid];
  if (tid < 32)  sbp[tid]  = bp[tid];
  if (tid < 128) sb1[tid]  = b1m[tid];
  if (tid < 32){ sg1[tid] = g1[tid]; sbe1[tid] = be1[tid]; sg2[tid] = g2[tid]; sbe2[tid] = be2[tid]; }
  if (tid < 225) sbt[tid] = btab[tid];

  #pragma unroll
  for (int i = 0; i < 8; i++){
    int q = tid + i*256; int gg = q>>9; int tt = (q>>3)&63; int j4 = q&7;
    int w = blockIdx.x*4 + gg; int bb = w>>12, rem = w&4095, wy = rem>>6, wx = rem&63;
    size_t tok = (size_t)bb*262144 + (size_t)(wy*8 + (tt>>3))*512 + wx*8 + (tt&7);
    *(float4*)(rg + gg*4608 + tt*RS + j4*4) = *(const float4*)(x + tok*32 + j4*4);
  }
  __syncthreads();

  const int g = tid >> 6, t = tid & 63;
  const int ty = t >> 3, tx = t & 7;
  float* A  = rg + g*4608;
  float* Bb = A + 2304;
  const int bbias = (tx + 7)*15 + (ty + 7);

  float vv[32];
  #pragma unroll
  for (int i = 0; i < 8; i++){
    float4 r = *(const float4*)(A + t*RS + 4*i);
    vv[4*i] = r.x; vv[4*i+1] = r.y; vv[4*i+2] = r.z; vv[4*i+3] = r.w;
  }
  float mu = 0.f;
  #pragma unroll
  for (int c = 0; c < 32; c++) mu += vv[c];
  mu *= (1.f/32.f);
  float var = 0.f;
  #pragma unroll
  for (int c = 0; c < 32; c++){ float d = vv[c]-mu; var += d*d; }
  var *= (1.f/32.f);
  float rs = rsqrtf(var + EPSc);
  u64 xu[16];
  #pragma unroll
  for (int i = 0; i < 16; i++){
    float a0 = (vv[2*i]  -mu)*rs*sg1[2*i]   + sbe1[2*i];
    float a1 = (vv[2*i+1]-mu)*rs*sg1[2*i+1] + sbe1[2*i+1];
    xu[i] = pack2(a0, a1);
  }

  u64 qu[16];
  #pragma unroll
  for (int i = 0; i < 16; i++){
    float a0 = leakyf(dot32s(xu, sWq + (2*i  )*32) + sbq[2*i  ]) * SCALEc;
    float a1 = leakyf(dot32s(xu, sWq + (2*i+1)*32) + sbq[2*i+1]) * SCALEc;
    qu[i] = pack2(a0, a1);
  }
  #pragma unroll 2
  for (int j = 0; j < 32; j += 4){
    float a0 = leakyf(dot32s(xu, sWkv + (j  )*32) + sbkv[j  ]);
    float a1 = leakyf(dot32s(xu, sWkv + (j+1)*32) + sbkv[j+1]);
    float a2 = leakyf(dot32s(xu, sWkv + (j+2)*32) + sbkv[j+2]);
    float a3 = leakyf(dot32s(xu, sWkv + (j+3)*32) + sbkv[j+3]);
    *(float4*)(Bb + t*RS + j) = make_float4(a0, a1, a2, a3);
  }
  #pragma unroll 2
  for (int j = 0; j < 32; j += 4){
    float a0 = leakyf(dot32s(xu, sWkv + (32+j  )*32) + sbkv[32+j  ]);
    float a1 = leakyf(dot32s(xu, sWkv + (32+j+1)*32) + sbkv[32+j+1]);
    float a2 = leakyf(dot32s(xu, sWkv + (32+j+2)*32) + sbkv[32+j+2]);
    float a3 = leakyf(dot32s(xu, sWkv + (32+j+3)*32) + sbkv[32+j+3]);
    *(float4*)(A + t*RS + j) = make_float4(a0, a1, a2, a3);
  }
  __syncthreads();

  float s[64];
  float mx = -3.0e38f;
  #pragma unroll
  for (int m = 0; m < 64; m++){
    float sc = dot32s(qu, Bb + m*RS) + sbt[bbias - ((m&7)*15 + (m>>3))];
    s[m] = sc; mx = fmaxf(mx, sc);
  }
  __syncthreads();

  #pragma unroll
  for (int i = 0; i < 8; i++){
    int q = tid + i*256; int gg = q>>9; int tt = (q>>3)&63; int j4 = q&7;
    int w = blockIdx.x*4 + gg; int bb = w>>12, rem = w&4095, wy = rem>>6, wx = rem&63;
    size_t tok = (size_t)bb*262144 + (size_t)(wy*8 + (tt>>3))*512 + wx*8 + (tt&7);
    *(float4*)(rg + gg*4608 + 2304 + tt*RS + j4*4) = *(const float4*)(x + tok*32 + j4*4);
  }

  float l = 0.f;
  #pragma unroll
  for (int m = 0; m < 64; m++){ float p = __expf(s[m]-mx); l += p; s[m] = p; }

  u64 Ou[16];
  #pragma unroll
  for (int i = 0; i < 16; i++) Ou[i] = 0ULL;
  #pragma unroll
  for (int m = 0; m < 64; m++){
    u64 pp = pack2(s[m], s[m]);
    const ulonglong2* vp = (const ulonglong2*)(A + m*RS);
    #pragma unroll
    for (int i = 0; i < 8; i++){
      ulonglong2 vq = vp[i];
      Ou[2*i]   = ffma2(pp, vq.x, Ou[2*i]);
      Ou[2*i+1] = ffma2(pp, vq.y, Ou[2*i+1]);
    }
  }
  {
    float linv = 1.f / l;
    u64 li = pack2(linv, linv);
    #pragma unroll
    for (int i = 0; i < 16; i++) Ou[i] = fmul2(Ou[i], li);
  }
  __syncthreads();

  float x2r[32];
  #pragma unroll 2
  for (int j = 0; j < 32; j++) x2r[j] = dot32s(Ou, sWp + j*32) + sbp[j];
  #pragma unroll
  for (int i = 0; i < 8; i++){
    float4 r = *(const float4*)(Bb + t*RS + 4*i);
    x2r[4*i] += r.x; x2r[4*i+1] += r.y; x2r[4*i+2] += r.z; x2r[4*i+3] += r.w;
  }
  #pragma unroll
  for (int i = 0; i < 8; i++)
    *(float4*)(A + t*RS + 4*i) = make_float4(x2r[4*i], x2r[4*i+1], x2r[4*i+2], x2r[4*i+3]);

  mu = 0.f;
  #pragma unroll
  for (int c = 0; c < 32; c++) mu += x2r[c];
  mu *= (1.f/32.f);
  var = 0.f;
  #pragma unroll
  for (int c = 0; c < 32; c++){ float d = x2r[c]-mu; var += d*d; }
  var *= (1.f/32.f);
  rs = rsqrtf(var + EPSc);
  u64 yu[16];
  #pragma unroll
  for (int i = 0; i < 16; i++){
    float a0 = (x2r[2*i]  -mu)*rs*sg2[2*i]   + sbe2[2*i];
    float a1 = (x2r[2*i+1]-mu)*rs*sg2[2*i+1] + sbe2[2*i+1];
    yu[i] = pack2(a0, a1);
  }
  __syncthreads();

  #pragma unroll
  for (int i = 0; i < 8; i++){
    int q = tid + i*256; int gg = q>>9; int tt = (q>>3)&63; int j4 = q&7;
    int w = blockIdx.x*4 + gg; int bb = w>>12, rem = w&4095, wy = rem>>6, wx = rem&63;
    size_t tok = (size_t)bb*262144 + (size_t)(wy*8 + (tt>>3))*512 + wx*8 + (tt&7);
    *(float4*)(g_x2 + tok*32 + j4*4) = *(const float4*)(rg + gg*4608 + tt*RS + j4*4);
  }
  __syncthreads();

  #pragma unroll 1
  for (int qt = 0; qt < 4; qt++){
    float hq[32];
    #pragma unroll 2
    for (int jj = 0; jj < 32; jj += 4){
      int j = qt*32 + jj;
      hq[jj  ] = geluf(dot32s(yu, sW1 + (j  )*32) + sb1[j  ]);
      hq[jj+1] = geluf(dot32s(yu, sW1 + (j+1)*32) + sb1[j+1]);
      hq[jj+2] = geluf(dot32s(yu, sW1 + (j+2)*32) + sb1[j+2]);
      hq[jj+3] = geluf(dot32s(yu, sW1 + (j+3)*32) + sb1[j+3]);
    }
    #pragma unroll
    for (int i = 0; i < 8; i++)
      *(float4*)(A + t*RS + 4*i) = make_float4(hq[4*i], hq[4*i+1], hq[4*i+2], hq[4*i+3]);
    __syncthreads();
    #pragma unroll
    for (int i = 0; i < 8; i++){
      int q = tid + i*256; int gg = q>>9; int tt = (q>>3)&63; int j4 = q&7;
      int w = blockIdx.x*4 + gg; int bb = w>>12, rem = w&4095, wy = rem>>6, wx = rem&63;
      size_t tok = (size_t)bb*262144 + (size_t)(wy*8 + (tt>>3))*512 + wx*8 + (tt&7);
      *(float4*)(g_h + tok*128 + qt*32 + j4*4) = *(const float4*)(rg + gg*4608 + tt*RS + j4*4);
    }
    __syncthreads();
  }
}

// ======================= K2 v4: column-streaming conv, g-major tile, 3 blocks/SM =======================
// tile layout: 32 channel-group regions (4 ch each), region stride 404 floats,
// slot (row*10+col)*4 within region. Conv: thread=(g,x) streams rows, weights in regs,
// 3-slot circular output accumulators, in-place h2 writeback gated by per-row barriers.
constexpr int RST = 404;
constexpr int K2_SMF = 5444 + 32*RST;   // 18372 floats = 73,488 B

__global__ void __launch_bounds__(256, 3) k2_leff(
    const float* __restrict__ dwk, const float* __restrict__ dwb,
    const float* __restrict__ W2,  const float* __restrict__ b2m,
    float* __restrict__ out)
{
  extern __shared__ float sm[];
  float* sW2  = sm;            // [128 k][32 c]
  float* sdw  = sm + 4096;     // [9 tap][128 ch] stride 132
  float* sdwb = sm + 5284;     // 128
  float* sb2  = sm + 5412;     // 32
  float* st   = sm + 5444;     // 32 regions x 404

  const int tid = threadIdx.x;
  for (int i = tid; i < 4096; i += 256) sW2[i] = W2[i];
  for (int i = tid; i < 1152; i += 256){
    int tap = i >> 7, c = i & 127;
    sdw[tap*132 + c] = dwk[i];
  }
  if (tid < 128) sdwb[tid] = dwb[tid];
  if (tid < 32)  sb2[tid]  = b2m[tid];

  const int blk = blockIdx.x, b = blk >> 12, rem = blk & 4095;
  const int y0 = (rem >> 6)*8, x0 = (rem & 63)*8;

  // ---- stage halo (g-major transposed layout) ----
  const int wid = tid >> 5, lane = tid & 31;
  for (int vid = wid; vid < 100; vid += 8){
    int r = vid/10, c = vid - r*10;
    int hy = y0 + r - 1, hx = x0 + c - 1;
    float4 val = make_float4(0.f, 0.f, 0.f, 0.f);
    if ((unsigned)hy < 512u && (unsigned)hx < 512u)
      val = *(const float4*)(g_h + ((size_t)b*262144 + (size_t)hy*512 + hx)*128 + lane*4);
    *(float4*)(st + lane*RST + vid*4) = val;
  }
  __syncthreads();

  // ---- conv: thread = (g 0..31, x 0..7) ----
  const int cx = tid & 7;
  const int cg = tid >> 3;
  float* gbase = st + cg*RST;

  u64 w[9][2];
  #pragma unroll
  for (int tp = 0; tp < 9; tp++){
    float4 wv = *(const float4*)(sdw + tp*132 + cg*4);
    w[tp][0] = pack2(wv.x, wv.y); w[tp][1] = pack2(wv.z, wv.w);
  }
  u64 bs0, bs1;
  { float4 bv = *(const float4*)(sdwb + cg*4); bs0 = pack2(bv.x, bv.y); bs1 = pack2(bv.z, bv.w); }

  u64 o3[3][2];
  #pragma unroll
  for (int y = 0; y < 10; y++){
    // rotate in accumulator for output tile-row y+1 (valid 1..8)
    if (y+1 <= 8){ o3[(y+1)%3][0] = bs0; o3[(y+1)%3][1] = bs1; }
    // read tile row y, cols cx..cx+2
    u64 r0[3], r1[3];
    #pragma unroll
    for (int kx = 0; kx < 3; kx++){
      float4 rr = *(const float4*)(gbase + (y*10 + cx + kx)*4);
      r0[kx] = pack2(rr.x, rr.y); r1[kx] = pack2(rr.z, rr.w);
    }
    if (y+1 <= 8){               // ky=0 -> ot=y+1
      const int sl = (y+1)%3;
      #pragma unroll
      for (int kx = 0; kx < 3; kx++){
        o3[sl][0] = ffma2(w[kx][0], r0[kx], o3[sl][0]);
        o3[sl][1] = ffma2(w[kx][1], r1[kx], o3[sl][1]);
      }
    }
    if (y >= 1 && y <= 8){       // ky=1 -> ot=y
      const int sl = y%3;
      #pragma unroll
      for (int kx = 0; kx < 3; kx++){
        o3[sl][0] = ffma2(w[3+kx][0], r0[kx], o3[sl][0]);
        o3[sl][1] = ffma2(w[3+kx][1], r1[kx], o3[sl][1]);
      }
    }
    if (y >= 2){                 // ky=2 -> ot=y-1
      const int sl = (y-1)%3;
      #pragma unroll
      for (int kx = 0; kx < 3; kx++){
        o3[sl][0] = ffma2(w[6+kx][0], r0[kx], o3[sl][0]);
        o3[sl][1] = ffma2(w[6+kx][1], r1[kx], o3[sl][1]);
      }
    }
    __syncthreads();             // row y fully consumed by all threads
    if (y >= 2){                 // finalize ot=y-1: gelu + in-place writeback
      const int ot = y-1, sl = (y-1)%3;
      float2 f0 = unpack2(o3[sl][0]), f1 = unpack2(o3[sl][1]);
      *(float4*)(gbase + (ot*10 + cx + 1)*4) =
          make_float4(geluf(f0.x), geluf(f0.y), geluf(f1.x), geluf(f1.y));
    }
  }
  __syncthreads();               // all h2 writebacks visible

  // ---- GEMM: thread = (gq = wid&3, p = pixel) ----
  const int gq = wid & 3;
  const int p  = (wid >> 2)*32 + lane;
  const int py = p >> 3, px = p & 7;
  const int slot = ((py+1)*10 + (px+1))*4;
  float4 h4[8];
  #pragma unroll
  for (int jj = 0; jj < 8; jj++)
    h4[jj] = *(const float4*)(st + (gq*8 + jj)*RST + slot);
  __syncthreads();               // h2 reads done -> st reusable as partial buffer

  u64 pacc[16];
  #pragma unroll
  for (int i = 0; i < 16; i++) pacc[i] = 0ULL;
  #pragma unroll 8
  for (int j = 0; j < 32; j++){
    float hvv = ((const float*)h4)[j];
    u64 hh = pack2(hvv, hvv);
    const ulonglong2* wr = (const ulonglong2*)(sW2 + (gq*32 + j)*32);
    #pragma unroll
    for (int i = 0; i < 8; i++){
      ulonglong2 wv = wr[i];
      pacc[2*i]   = ffma2(hh, wv.x, pacc[2*i]);
      pacc[2*i+1] = ffma2(hh, wv.y, pacc[2*i+1]);
    }
  }
  {
    float* prow = st + p*132 + gq*32;
    #pragma unroll
    for (int i = 0; i < 8; i++){
      float2 f0 = unpack2(pacc[2*i]), f1 = unpack2(pacc[2*i+1]);
      *(float4*)(prow + 4*i) = make_float4(f0.x, f0.y, f1.x, f1.y);
    }
  }
  __syncthreads();

  // ---- reduce 4 partials + bias + residual ----
  const int p3 = tid >> 2, g3 = tid & 3, c0 = g3*8;
  float o[8];
  #pragma unroll
  for (int i = 0; i < 8; i++) o[i] = sb2[c0+i];
  #pragma unroll
  for (int gp = 0; gp < 4; gp++){
    const float* pr = st + p3*132 + gp*32 + c0;
    float4 a = *(const float4*)(pr);
    float4 bq4 = *(const float4*)(pr + 4);
    o[0]+=a.x; o[1]+=a.y; o[2]+=a.z; o[3]+=a.w;
    o[4]+=bq4.x; o[5]+=bq4.y; o[6]+=bq4.z; o[7]+=bq4.w;
  }
  const int yy = y0 + (p3>>3), xx = x0 + (p3&7);
  const size_t pbase = ((size_t)b*262144 + (size_t)yy*512 + xx)*32 + c0;
  float4 xa = *(const float4*)(g_x2 + pbase);
  float4 xb = *(const float4*)(g_x2 + pbase + 4);
  *(float4*)(out + pbase)     = make_float4(o[0]+xa.x, o[1]+xa.y, o[2]+xa.z, o[3]+xa.w);
  *(float4*)(out + pbase + 4) = make_float4(o[4]+xb.x, o[5]+xb.y, o[6]+xb.z, o[7]+xb.w);
}

// ======================= launch =======================
extern "C" void kernel_launch(void* const* d_in, const int* in_sizes, int n_in,
                              void* d_out, int out_size)
{
  (void)in_sizes; (void)n_in; (void)out_size;
  const float* x    = (const float*)d_in[0];
  const float* g1   = (const float*)d_in[1];
  const float* be1  = (const float*)d_in[2];
  const float* Wq   = (const float*)d_in[3];
  const float* bq   = (const float*)d_in[4];
  const float* Wkv  = (const float*)d_in[5];
  const float* bkv  = (const float*)d_in[6];
  const float* btab = (const float*)d_in[7];
  const float* Wp   = (const float*)d_in[8];
  const float* bp   = (const float*)d_in[9];
  const float* g2   = (const float*)d_in[10];
  const float* be2  = (const float*)d_in[11];
  const float* W1   = (const float*)d_in[12];
  const float* b1m  = (const float*)d_in[13];
  const float* dwk  = (const float*)d_in[14];
  const float* dwb  = (const float*)d_in[15];
  const float* W2   = (const float*)d_in[16];
  const float* b2m  = (const float*)d_in[17];
  float* out = (float*)d_out;

  cudaFuncSetAttribute(k1_attn, cudaFuncAttributeMaxDynamicSharedMemorySize, K1_SMF*4);
  cudaFuncSetAttribute(k2_leff, cudaFuncAttributeMaxDynamicSharedMemorySize, K2_SMF*4);

  k1_attn<<<2048, 256, K1_SMF*4>>>(x, g1, be1, Wq, bq, Wkv, bkv, btab, Wp, bp, g2, be2, W1, b1m);
  k2_leff<<<8192, 256, K2_SMF*4>>>(dwk, dwb, W2, b2m, out);
}

// round 17
// speedup vs baseline: 1.2764x; 1.0027x over previous
#include <cuda_runtime.h>
#include <cstdint>

#define DEV __device__ __forceinline__
typedef unsigned long long u64;

DEV u64 ffma2(u64 a, u64 b, u64 c){ u64 d; asm("fma.rn.f32x2 %0, %1, %2, %3;" : "=l"(d) : "l"(a), "l"(b), "l"(c)); return d; }
DEV u64 fmul2(u64 a, u64 b){ u64 d; asm("mul.rn.f32x2 %0, %1, %2;" : "=l"(d) : "l"(a), "l"(b)); return d; }
DEV u64 fadd2(u64 a, u64 b){ u64 d; asm("add.rn.f32x2 %0, %1, %2;" : "=l"(d) : "l"(a), "l"(b)); return d; }
DEV u64 pack2(float lo, float hi){ u64 r; asm("mov.b64 %0, {%1,%2};" : "=l"(r) : "f"(lo), "f"(hi)); return r; }
DEV float2 unpack2(u64 v){ float2 r; asm("mov.b64 {%0,%1}, %2;" : "=f"(r.x), "=f"(r.y) : "l"(v)); return r; }
DEV float rcpf(float a){ float r; asm("rcp.approx.f32 %0, %1;" : "=f"(r) : "f"(a)); return r; }

DEV float dot32s(const u64* a, const float* __restrict__ w){
  u64 acc0 = 0ULL, acc1 = 0ULL;
  const ulonglong2* wp = (const ulonglong2*)w;
  #pragma unroll
  for (int i = 0; i < 8; i++){
    ulonglong2 wv = wp[i];
    acc0 = ffma2(a[2*i],   wv.x, acc0);
    acc1 = ffma2(a[2*i+1], wv.y, acc1);
  }
  float2 f = unpack2(fadd2(acc0, acc1));
  return f.x + f.y;
}

DEV float leakyf(float z){ return fmaxf(z, 0.3f*z); }

// exact-enough GELU: erf via Abramowitz-Stegun 7.1.26 (|abs err| <= 1.5e-7), branch-free
DEV float geluf(float z){
  float x = fabsf(z) * 0.70710678118654752440f;
  float t = rcpf(fmaf(0.3275911f, x, 1.0f));
  float p = t * fmaf(t, fmaf(t, fmaf(t, fmaf(t, 1.061405429f, -1.453152027f),
                                     1.421413741f), -0.284496736f), 0.254829592f);
  float e = __expf(-x*x);
  float erfv = fmaf(-p, e, 1.0f);          // erf(|x|) in [0,1)
  float s = copysignf(erfv, z);            // sign(z)*erf(|x|)
  return 0.5f*z*(1.0f + s);
}

constexpr float SCALEc = 0.17677669529663688f;
constexpr float EPSc = 1e-3f;

__device__ float g_h [(size_t)2*512*512*128];   // 256 MB
__device__ float g_x2[(size_t)2*512*512*32];    // 64 MB

// ======================= K1 (A/B regions, 2 blocks/SM; fast gelu + hoisted h-write addressing) =======================
constexpr int RS = 36;
constexpr int K1_SMF = 8816 + 4*4608;   // 27248 floats = 108,992 B

__global__ void __launch_bounds__(256, 2) k1_attn(
    const float* __restrict__ x,  const float* __restrict__ g1, const float* __restrict__ be1,
    const float* __restrict__ Wq, const float* __restrict__ bq,
    const float* __restrict__ Wkv,const float* __restrict__ bkv,
    const float* __restrict__ btab,
    const float* __restrict__ Wp, const float* __restrict__ bp,
    const float* __restrict__ g2, const float* __restrict__ be2,
    const float* __restrict__ W1, const float* __restrict__ b1m)
{
  extern __shared__ float sm[];
  float* sWq  = sm;
  float* sWkv = sm + 1024;
  float* sWp  = sm + 3072;
  float* sW1  = sm + 4096;
  float* svec = sm + 8192;
  float* sbt  = sm + 8576;
  float* rg   = sm + 8816;
  float* sbq  = svec;       float* sbkv = svec + 32;  float* sbp  = svec + 96;  float* sb1 = svec + 128;
  float* sg1  = svec + 256; float* sbe1 = svec + 288; float* sg2  = svec + 320; float* sbe2 = svec + 352;

  const int tid = threadIdx.x;
  for (int i = tid; i < 1024; i += 256) sWq [(i&31)*32 + (i>>5)]  = Wq[i];
  for (int i = tid; i < 2048; i += 256) sWkv[(i&63)*32 + (i>>6)]  = Wkv[i];
  for (int i = tid; i < 1024; i += 256) sWp [(i&31)*32 + (i>>5)]  = Wp[i];
  for (int i = tid; i < 4096; i += 256) sW1 [(i&127)*32 + (i>>7)] = W1[i];
  if (tid < 32)  sbq[tid]  = bq[tid];
  if (tid < 64)  sbkv[tid] = bkv[tid];
  if (tid < 32)  sbp[tid]  = bp[tid];
  if (tid < 128) sb1[tid]  = b1m[tid];
  if (tid < 32){ sg1[tid] = g1[tid]; sbe1[tid] = be1[tid]; sg2[tid] = g2[tid]; sbe2[tid] = be2[tid]; }
  if (tid < 225) sbt[tid] = btab[tid];

  #pragma unroll
  for (int i = 0; i < 8; i++){
    int q = tid + i*256; int gg = q>>9; int tt = (q>>3)&63; int j4 = q&7;
    int w = blockIdx.x*4 + gg; int bb = w>>12, rem = w&4095, wy = rem>>6, wx = rem&63;
    size_t tok = (size_t)bb*262144 + (size_t)(wy*8 + (tt>>3))*512 + wx*8 + (tt&7);
    *(float4*)(rg + gg*4608 + tt*RS + j4*4) = *(const float4*)(x + tok*32 + j4*4);
  }
  __syncthreads();

  const int g = tid >> 6, t = tid & 63;
  const int ty = t >> 3, tx = t & 7;
  float* A  = rg + g*4608;
  float* Bb = A + 2304;
  const int bbias = (tx + 7)*15 + (ty + 7);

  float vv[32];
  #pragma unroll
  for (int i = 0; i < 8; i++){
    float4 r = *(const float4*)(A + t*RS + 4*i);
    vv[4*i] = r.x; vv[4*i+1] = r.y; vv[4*i+2] = r.z; vv[4*i+3] = r.w;
  }
  float mu = 0.f;
  #pragma unroll
  for (int c = 0; c < 32; c++) mu += vv[c];
  mu *= (1.f/32.f);
  float var = 0.f;
  #pragma unroll
  for (int c = 0; c < 32; c++){ float d = vv[c]-mu; var += d*d; }
  var *= (1.f/32.f);
  float rs = rsqrtf(var + EPSc);
  u64 xu[16];
  #pragma unroll
  for (int i = 0; i < 16; i++){
    float a0 = (vv[2*i]  -mu)*rs*sg1[2*i]   + sbe1[2*i];
    float a1 = (vv[2*i+1]-mu)*rs*sg1[2*i+1] + sbe1[2*i+1];
    xu[i] = pack2(a0, a1);
  }

  u64 qu[16];
  #pragma unroll
  for (int i = 0; i < 16; i++){
    float a0 = leakyf(dot32s(xu, sWq + (2*i  )*32) + sbq[2*i  ]) * SCALEc;
    float a1 = leakyf(dot32s(xu, sWq + (2*i+1)*32) + sbq[2*i+1]) * SCALEc;
    qu[i] = pack2(a0, a1);
  }
  #pragma unroll 2
  for (int j = 0; j < 32; j += 4){
    float a0 = leakyf(dot32s(xu, sWkv + (j  )*32) + sbkv[j  ]);
    float a1 = leakyf(dot32s(xu, sWkv + (j+1)*32) + sbkv[j+1]);
    float a2 = leakyf(dot32s(xu, sWkv + (j+2)*32) + sbkv[j+2]);
    float a3 = leakyf(dot32s(xu, sWkv + (j+3)*32) + sbkv[j+3]);
    *(float4*)(Bb + t*RS + j) = make_float4(a0, a1, a2, a3);
  }
  #pragma unroll 2
  for (int j = 0; j < 32; j += 4){
    float a0 = leakyf(dot32s(xu, sWkv + (32+j  )*32) + sbkv[32+j  ]);
    float a1 = leakyf(dot32s(xu, sWkv + (32+j+1)*32) + sbkv[32+j+1]);
    float a2 = leakyf(dot32s(xu, sWkv + (32+j+2)*32) + sbkv[32+j+2]);
    float a3 = leakyf(dot32s(xu, sWkv + (32+j+3)*32) + sbkv[32+j+3]);
    *(float4*)(A + t*RS + j) = make_float4(a0, a1, a2, a3);
  }
  __syncthreads();

  float s[64];
  float mx = -3.0e38f;
  #pragma unroll
  for (int m = 0; m < 64; m++){
    float sc = dot32s(qu, Bb + m*RS) + sbt[bbias - ((m&7)*15 + (m>>3))];
    s[m] = sc; mx = fmaxf(mx, sc);
  }
  __syncthreads();

  #pragma unroll
  for (int i = 0; i < 8; i++){
    int q = tid + i*256; int gg = q>>9; int tt = (q>>3)&63; int j4 = q&7;
    int w = blockIdx.x*4 + gg; int bb = w>>12, rem = w&4095, wy = rem>>6, wx = rem&63;
    size_t tok = (size_t)bb*262144 + (size_t)(wy*8 + (tt>>3))*512 + wx*8 + (tt&7);
    *(float4*)(rg + gg*4608 + 2304 + tt*RS + j4*4) = *(const float4*)(x + tok*32 + j4*4);
  }

  float l = 0.f;
  #pragma unroll
  for (int m = 0; m < 64; m++){ float p = __expf(s[m]-mx); l += p; s[m] = p; }

  u64 Ou[16];
  #pragma unroll
  for (int i = 0; i < 16; i++) Ou[i] = 0ULL;
  #pragma unroll
  for (int m = 0; m < 64; m++){
    u64 pp = pack2(s[m], s[m]);
    const ulonglong2* vp = (const ulonglong2*)(A + m*RS);
    #pragma unroll
    for (int i = 0; i < 8; i++){
      ulonglong2 vq = vp[i];
      Ou[2*i]   = ffma2(pp, vq.x, Ou[2*i]);
      Ou[2*i+1] = ffma2(pp, vq.y, Ou[2*i+1]);
    }
  }
  {
    float linv = rcpf(l);
    // one Newton step for safety: linv*(2 - l*linv)
    linv = linv * (2.0f - l*linv);
    u64 li = pack2(linv, linv);
    #pragma unroll
    for (int i = 0; i < 16; i++) Ou[i] = fmul2(Ou[i], li);
  }
  __syncthreads();

  float x2r[32];
  #pragma unroll 2
  for (int j = 0; j < 32; j++) x2r[j] = dot32s(Ou, sWp + j*32) + sbp[j];
  #pragma unroll
  for (int i = 0; i < 8; i++){
    float4 r = *(const float4*)(Bb + t*RS + 4*i);
    x2r[4*i] += r.x; x2r[4*i+1] += r.y; x2r[4*i+2] += r.z; x2r[4*i+3] += r.w;
  }
  #pragma unroll
  for (int i = 0; i < 8; i++)
    *(float4*)(A + t*RS + 4*i) = make_float4(x2r[4*i], x2r[4*i+1], x2r[4*i+2], x2r[4*i+3]);

  mu = 0.f;
  #pragma unroll
  for (int c = 0; c < 32; c++) mu += x2r[c];
  mu *= (1.f/32.f);
  var = 0.f;
  #pragma unroll
  for (int c = 0; c < 32; c++){ float d = x2r[c]-mu; var += d*d; }
  var *= (1.f/32.f);
  rs = rsqrtf(var + EPSc);
  u64 yu[16];
  #pragma unroll
  for (int i = 0; i < 16; i++){
    float a0 = (x2r[2*i]  -mu)*rs*sg2[2*i]   + sbe2[2*i];
    float a1 = (x2r[2*i+1]-mu)*rs*sg2[2*i+1] + sbe2[2*i+1];
    yu[i] = pack2(a0, a1);
  }
  __syncthreads();

  #pragma unroll
  for (int i = 0; i < 8; i++){
    int q = tid + i*256; int gg = q>>9; int tt = (q>>3)&63; int j4 = q&7;
    int w = blockIdx.x*4 + gg; int bb = w>>12, rem = w&4095, wy = rem>>6, wx = rem&63;
    size_t tok = (size_t)bb*262144 + (size_t)(wy*8 + (tt>>3))*512 + wx*8 + (tt&7);
    *(float4*)(g_x2 + tok*32 + j4*4) = *(const float4*)(rg + gg*4608 + tt*RS + j4*4);
  }
  __syncthreads();

  // hoisted coop addressing for h-write (xu/qu/s dead here; 16 ints are phase-local)
  int soff[8], goff[8];
  #pragma unroll
  for (int i = 0; i < 8; i++){
    int q = tid + i*256; int gg = q>>9; int tt = (q>>3)&63; int j4 = q&7;
    int w = blockIdx.x*4 + gg; int bb = w>>12, rem = w&4095, wy = rem>>6, wx = rem&63;
    int tok = bb*262144 + (wy*8 + (tt>>3))*512 + wx*8 + (tt&7);
    soff[i] = gg*4608 + tt*RS + j4*4;
    goff[i] = tok*128 + j4*4;
  }

  #pragma unroll 1
  for (int qt = 0; qt < 4; qt++){
    float hq[32];
    #pragma unroll 2
    for (int jj = 0; jj < 32; jj += 4){
      int j = qt*32 + jj;
      hq[jj  ] = geluf(dot32s(yu, sW1 + (j  )*32) + sb1[j  ]);
      hq[jj+1] = geluf(dot32s(yu, sW1 + (j+1)*32) + sb1[j+1]);
      hq[jj+2] = geluf(dot32s(yu, sW1 + (j+2)*32) + sb1[j+2]);
      hq[jj+3] = geluf(dot32s(yu, sW1 + (j+3)*32) + sb1[j+3]);
    }
    #pragma unroll
    for (int i = 0; i < 8; i++)
      *(float4*)(A + t*RS + 4*i) = make_float4(hq[4*i], hq[4*i+1], hq[4*i+2], hq[4*i+3]);
    __syncthreads();
    #pragma unroll
    for (int i = 0; i < 8; i++)
      *(float4*)(g_h + goff[i] + qt*32) = *(const float4*)(rg + soff[i]);
    __syncthreads();
  }
}

// ======================= K2 v4 (column-streaming conv, fast gelu) =======================
constexpr int RST = 404;
constexpr int K2_SMF = 5444 + 32*RST;   // 18372 floats = 73,488 B

__global__ void __launch_bounds__(256, 3) k2_leff(
    const float* __restrict__ dwk, const float* __restrict__ dwb,
    const float* __restrict__ W2,  const float* __restrict__ b2m,
    float* __restrict__ out)
{
  extern __shared__ float sm[];
  float* sW2  = sm;            // [128 k][32 c]
  float* sdw  = sm + 4096;     // [9 tap][128 ch] stride 132
  float* sdwb = sm + 5284;     // 128
  float* sb2  = sm + 5412;     // 32
  float* st   = sm + 5444;     // 32 regions x 404

  const int tid = threadIdx.x;
  for (int i = tid; i < 4096; i += 256) sW2[i] = W2[i];
  for (int i = tid; i < 1152; i += 256){
    int tap = i >> 7, c = i & 127;
    sdw[tap*132 + c] = dwk[i];
  }
  if (tid < 128) sdwb[tid] = dwb[tid];
  if (tid < 32)  sb2[tid]  = b2m[tid];

  const int blk = blockIdx.x, b = blk >> 12, rem = blk & 4095;
  const int y0 = (rem >> 6)*8, x0 = (rem & 63)*8;

  const int wid = tid >> 5, lane = tid & 31;
  for (int vid = wid; vid < 100; vid += 8){
    int r = vid/10, c = vid - r*10;
    int hy = y0 + r - 1, hx = x0 + c - 1;
    float4 val = make_float4(0.f, 0.f, 0.f, 0.f);
    if ((unsigned)hy < 512u && (unsigned)hx < 512u)
      val = *(const float4*)(g_h + ((size_t)b*262144 + (size_t)hy*512 + hx)*128 + lane*4);
    *(float4*)(st + lane*RST + vid*4) = val;
  }
  __syncthreads();

  const int cx = tid & 7;
  const int cg = tid >> 3;
  float* gbase = st + cg*RST;

  u64 w[9][2];
  #pragma unroll
  for (int tp = 0; tp < 9; tp++){
    float4 wv = *(const float4*)(sdw + tp*132 + cg*4);
    w[tp][0] = pack2(wv.x, wv.y); w[tp][1] = pack2(wv.z, wv.w);
  }
  u64 bs0, bs1;
  { float4 bv = *(const float4*)(sdwb + cg*4); bs0 = pack2(bv.x, bv.y); bs1 = pack2(bv.z, bv.w); }

  u64 o3[3][2];
  #pragma unroll
  for (int y = 0; y < 10; y++){
    if (y+1 <= 8){ o3[(y+1)%3][0] = bs0; o3[(y+1)%3][1] = bs1; }
    u64 r0[3], r1[3];
    #pragma unroll
    for (int kx = 0; kx < 3; kx++){
      float4 rr = *(const float4*)(gbase + (y*10 + cx + kx)*4);
      r0[kx] = pack2(rr.x, rr.y); r1[kx] = pack2(rr.z, rr.w);
    }
    if (y+1 <= 8){
      const int sl = (y+1)%3;
      #pragma unroll
      for (int kx = 0; kx < 3; kx++){
        o3[sl][0] = ffma2(w[kx][0], r0[kx], o3[sl][0]);
        o3[sl][1] = ffma2(w[kx][1], r1[kx], o3[sl][1]);
      }
    }
    if (y >= 1 && y <= 8){
      const int sl = y%3;
      #pragma unroll
      for (int kx = 0; kx < 3; kx++){
        o3[sl][0] = ffma2(w[3+kx][0], r0[kx], o3[sl][0]);
        o3[sl][1] = ffma2(w[3+kx][1], r1[kx], o3[sl][1]);
      }
    }
    if (y >= 2){
      const int sl = (y-1)%3;
      #pragma unroll
      for (int kx = 0; kx < 3; kx++){
        o3[sl][0] = ffma2(w[6+kx][0], r0[kx], o3[sl][0]);
        o3[sl][1] = ffma2(w[6+kx][1], r1[kx], o3[sl][1]);
      }
    }
    __syncthreads();
    if (y >= 2){
      const int ot = y-1, sl = (y-1)%3;
      float2 f0 = unpack2(o3[sl][0]), f1 = unpack2(o3[sl][1]);
      *(float4*)(gbase + (ot*10 + cx + 1)*4) =
          make_float4(geluf(f0.x), geluf(f0.y), geluf(f1.x), geluf(f1.y));
    }
  }
  __syncthreads();

  const int gq = wid & 3;
  const int p  = (wid >> 2)*32 + lane;
  const int py = p >> 3, px = p & 7;
  const int slot = ((py+1)*10 + (px+1))*4;
  float4 h4[8];
  #pragma unroll
  for (int jj = 0; jj < 8; jj++)
    h4[jj] = *(const float4*)(st + (gq*8 + jj)*RST + slot);
  __syncthreads();

  u64 pacc[16];
  #pragma unroll
  for (int i = 0; i < 16; i++) pacc[i] = 0ULL;
  #pragma unroll 8
  for (int j = 0; j < 32; j++){
    float hvv = ((const float*)h4)[j];
    u64 hh = pack2(hvv, hvv);
    const ulonglong2* wr = (const ulonglong2*)(sW2 + (gq*32 + j)*32);
    #pragma unroll
    for (int i = 0; i < 8; i++){
      ulonglong2 wv = wr[i];
      pacc[2*i]   = ffma2(hh, wv.x, pacc[2*i]);
      pacc[2*i+1] = ffma2(hh, wv.y, pacc[2*i+1]);
    }
  }
  {
    float* prow = st + p*132 + gq*32;
    #pragma unroll
    for (int i = 0; i < 8; i++){
      float2 f0 = unpack2(pacc[2*i]), f1 = unpack2(pacc[2*i+1]);
      *(float4*)(prow + 4*i) = make_float4(f0.x, f0.y, f1.x, f1.y);
    }
  }
  __syncthreads();

  const int p3 = tid >> 2, g3 = tid & 3, c0 = g3*8;
  float o[8];
  #pragma unroll
  for (int i = 0; i < 8; i++) o[i] = sb2[c0+i];
  #pragma unroll
  for (int gp = 0; gp < 4; gp++){
    const float* pr = st + p3*132 + gp*32 + c0;
    float4 a = *(const float4*)(pr);
    float4 bq4 = *(const float4*)(pr + 4);
    o[0]+=a.x; o[1]+=a.y; o[2]+=a.z; o[3]+=a.w;
    o[4]+=bq4.x; o[5]+=bq4.y; o[6]+=bq4.z; o[7]+=bq4.w;
  }
  const int yy = y0 + (p3>>3), xx = x0 + (p3&7);
  const size_t pbase = ((size_t)b*262144 + (size_t)yy*512 + xx)*32 + c0;
  float4 xa = *(const float4*)(g_x2 + pbase);
  float4 xb = *(const float4*)(g_x2 + pbase + 4);
  *(float4*)(out + pbase)     = make_float4(o[0]+xa.x, o[1]+xa.y, o[2]+xa.z, o[3]+xa.w);
  *(float4*)(out + pbase + 4) = make_float4(o[4]+xb.x, o[5]+xb.y, o[6]+xb.z, o[7]+xb.w);
}

// ======================= launch =======================
extern "C" void kernel_launch(void* const* d_in, const int* in_sizes, int n_in,
                              void* d_out, int out_size)
{
  (void)in_sizes; (void)n_in; (void)out_size;
  const float* x    = (const float*)d_in[0];
  const float* g1   = (const float*)d_in[1];
  const float* be1  = (const float*)d_in[2];
  const float* Wq   = (const float*)d_in[3];
  const float* bq   = (const float*)d_in[4];
  const float* Wkv  = (const float*)d_in[5];
  const float* bkv  = (const float*)d_in[6];
  const float* btab = (const float*)d_in[7];
  const float* Wp   = (const float*)d_in[8];
  const float* bp   = (const float*)d_in[9];
  const float* g2   = (const float*)d_in[10];
  const float* be2  = (const float*)d_in[11];
  const float* W1   = (const float*)d_in[12];
  const float* b1m  = (const float*)d_in[13];
  const float* dwk  = (const float*)d_in[14];
  const float* dwb  = (const float*)d_in[15];
  const float* W2   = (const float*)d_in[16];
  const float* b2m  = (const float*)d_in[17];
  float* out = (float*)d_out;

  cudaFuncSetAttribute(k1_attn, cudaFuncAttributeMaxDynamicSharedMemorySize, K1_SMF*4);
  cudaFuncSetAttribute(k2_leff, cudaFuncAttributeMaxDynamicSharedMemorySize, K2_SMF*4);

  k1_attn<<<2048, 256, K1_SMF*4>>>(x, g1, be1, Wq, bq, Wkv, bkv, btab, Wp, bp, g2, be2, W1, b1m);
  k2_leff<<<8192, 256, K2_SMF*4>>>(dwk, dwb, W2, b2m, out);
}